// round 1
// baseline (speedup 1.0000x reference)
#include <cuda_runtime.h>

#define Nn   1024
#define Cc   64
#define HID  128
#define TILE 32
#define NT   (Nn / TILE)      // 32 tiles per dim
#define NPAIRS (NT * (NT + 1) / 2)  // 528
#define HCH  64               // h chunk staged in shared

__device__ float g_pi[HID * Nn];
__device__ float g_pj[HID * Nn];

__device__ __forceinline__ float tanh_approx(float x) {
    float y;
    asm("tanh.approx.f32 %0, %1;" : "=f"(y) : "f"(x));
    return y;
}

// ---------------------------------------------------------------------------
// Pre-pass: pi[h,n] = sum_c W1[h, C+c] * tanh(x[c,n]) + b1[h]
//           pj[h,n] = sum_c W1[h,   c] * tanh(x[c,n])
// grid = 64 blocks (n-chunks of 16), block = 128 threads (one h each)
// ---------------------------------------------------------------------------
#define NCH 16
__global__ void prep_kernel(const float* __restrict__ x,
                            const float* __restrict__ W1,
                            const float* __restrict__ b1) {
    __shared__ float t_s[Cc][NCH];
    const int n0  = blockIdx.x * NCH;
    const int tid = threadIdx.x;

    for (int k = tid; k < Cc * NCH; k += 128) {
        int c = k / NCH, n = k % NCH;
        t_s[c][n] = tanhf(x[c * Nn + n0 + n]);   // precise tanh here
    }
    __syncthreads();

    const int h = tid;
    float accj[NCH], acci[NCH];
    const float bb = b1[h];
#pragma unroll
    for (int n = 0; n < NCH; n++) { accj[n] = 0.0f; acci[n] = bb; }

#pragma unroll
    for (int c = 0; c < Cc; c++) {
        float wj = W1[h * (2 * Cc) + c];
        float wi = W1[h * (2 * Cc) + Cc + c];
#pragma unroll
        for (int n = 0; n < NCH; n++) {
            float t = t_s[c][n];
            accj[n] = fmaf(wj, t, accj[n]);
            acci[n] = fmaf(wi, t, acci[n]);
        }
    }
#pragma unroll
    for (int n = 0; n < NCH; n++) {
        g_pj[h * Nn + n0 + n] = accj[n];
        g_pi[h * Nn + n0 + n] = acci[n];
    }
}

// ---------------------------------------------------------------------------
// Main: for tile pair (ti <= tj), compute
//   e[i,j]  = sum_h W2[h] * tanh(pi[h,i] + pj[h,j])
//   e[j,i]  = sum_h W2[h] * tanh(pi[h,j] + pj[h,i])
//   out[i,j] = out[j,i] = e[i,j] + e[j,i] + 2*b2
// block = 256 threads: thread -> (il = tid/8, 4 consecutive j at (tid%8)*4)
// ---------------------------------------------------------------------------
__global__ void pair_kernel(const float* __restrict__ W2,
                            const float* __restrict__ b2,
                            float* __restrict__ out) {
    __shared__ __align__(16) float piI[HCH * TILE];
    __shared__ __align__(16) float pjJ[HCH * TILE];
    __shared__ __align__(16) float piJ[HCH * TILE];
    __shared__ __align__(16) float pjI[HCH * TILE];
    __shared__ float w2_s[HID];

    // decode triangular pair index
    int rem = blockIdx.x, ti = 0, rowlen = NT;
    while (rem >= rowlen) { rem -= rowlen; ti++; rowlen--; }
    const int tj = ti + rem;
    const int i0 = ti * TILE, j0 = tj * TILE;

    const int tid = threadIdx.x;
    if (tid < HID) w2_s[tid] = W2[tid];

    const int il = tid >> 3;          // 0..31
    const int jl = (tid & 7) * 4;     // 0,4,...,28

    float acc_e[4] = {0.f, 0.f, 0.f, 0.f};
    float acc_t[4] = {0.f, 0.f, 0.f, 0.f};

    for (int hc = 0; hc < HID / HCH; hc++) {
        __syncthreads();
        // stage HCH x TILE of each of the 4 operand tiles (float4 loads)
        for (int k = tid; k < HCH * TILE / 4; k += 256) {
            int hl = k >> 3;               // TILE/4 = 8
            int q  = (k & 7) * 4;
            int hg = hc * HCH + hl;
            ((float4*)piI)[k] = *(const float4*)&g_pi[hg * Nn + i0 + q];
            ((float4*)pjJ)[k] = *(const float4*)&g_pj[hg * Nn + j0 + q];
            ((float4*)piJ)[k] = *(const float4*)&g_pi[hg * Nn + j0 + q];
            ((float4*)pjI)[k] = *(const float4*)&g_pj[hg * Nn + i0 + q];
        }
        __syncthreads();

#pragma unroll 4
        for (int hl = 0; hl < HCH; hl++) {
            float w2 = w2_s[hc * HCH + hl];
            float ae = piI[hl * TILE + il];     // pi[h,i]
            float at = pjI[hl * TILE + il];     // pj[h,i]
            float4 bj = *(float4*)&pjJ[hl * TILE + jl];  // pj[h,j..j+3]
            float4 bi = *(float4*)&piJ[hl * TILE + jl];  // pi[h,j..j+3]

            acc_e[0] = fmaf(w2, tanh_approx(ae + bj.x), acc_e[0]);
            acc_e[1] = fmaf(w2, tanh_approx(ae + bj.y), acc_e[1]);
            acc_e[2] = fmaf(w2, tanh_approx(ae + bj.z), acc_e[2]);
            acc_e[3] = fmaf(w2, tanh_approx(ae + bj.w), acc_e[3]);

            acc_t[0] = fmaf(w2, tanh_approx(bi.x + at), acc_t[0]);
            acc_t[1] = fmaf(w2, tanh_approx(bi.y + at), acc_t[1]);
            acc_t[2] = fmaf(w2, tanh_approx(bi.z + at), acc_t[2]);
            acc_t[3] = fmaf(w2, tanh_approx(bi.w + at), acc_t[3]);
        }
    }

    const float bb2 = 2.0f * b2[0];
    const int gi = i0 + il;
    float4 o;
    o.x = acc_e[0] + acc_t[0] + bb2;
    o.y = acc_e[1] + acc_t[1] + bb2;
    o.z = acc_e[2] + acc_t[2] + bb2;
    o.w = acc_e[3] + acc_t[3] + bb2;

    // upper tile (row-contiguous)
    *(float4*)&out[gi * Nn + j0 + jl] = o;
    // mirrored lower tile (same values by symmetry)
    out[(j0 + jl + 0) * Nn + gi] = o.x;
    out[(j0 + jl + 1) * Nn + gi] = o.y;
    out[(j0 + jl + 2) * Nn + gi] = o.z;
    out[(j0 + jl + 3) * Nn + gi] = o.w;
}

extern "C" void kernel_launch(void* const* d_in, const int* in_sizes, int n_in,
                              void* d_out, int out_size) {
    const float* x  = (const float*)d_in[0];
    const float* W1 = (const float*)d_in[1];
    const float* b1 = (const float*)d_in[2];
    const float* W2 = (const float*)d_in[3];
    const float* b2 = (const float*)d_in[4];
    float* out = (float*)d_out;

    prep_kernel<<<Nn / NCH, 128>>>(x, W1, b1);
    pair_kernel<<<NPAIRS, 256>>>(W2, b2, out);
}